// round 2
// baseline (speedup 1.0000x reference)
#include <cuda_runtime.h>
#include <math.h>

#define NN 2048
#define TT 20
#define KK 32
#define CC 32
#define OO 64
#define G4 256   // 4*OO

// Scratch (static device globals; no runtime allocation)
__device__ float g_z[TT * NN * OO];        // z[t][n][o] = x[n][t] . conv_w[o]
__device__ float g_feat[TT * NN * OO];     // feat[t][n][o]
__device__ float g_gates[TT * NN * G4];    // gates_x[t][n][0..255]

typedef unsigned long long u64;

__device__ __forceinline__ void ffma2(u64& d, u64 a, u64 b) {
    asm("fma.rn.f32x2 %0, %1, %2, %0;" : "+l"(d) : "l"(a), "l"(b));
}
__device__ __forceinline__ float2 unpack2(u64 v) {
    float2 r;
    asm("mov.b64 {%0,%1}, %2;" : "=f"(r.x), "=f"(r.y) : "l"(v));
    return r;
}

__device__ __forceinline__ float sigf(float x) {
    return __fdividef(1.0f, 1.0f + __expf(-x));
}

// ---------------------------------------------------------------------------
// K1: z[t][n][o] = sum_c x[n][t][c] * conv_w[o][c]
// ---------------------------------------------------------------------------
__global__ __launch_bounds__(256) void k1_project(const float* __restrict__ x,
                                                  const float* __restrict__ conv_w) {
    __shared__ float cwT[CC * OO];      // cwT[c*64 + o]
    __shared__ float xs[8][CC];

    const int tid = threadIdx.x;
    for (int e = tid; e < OO * CC; e += 256) {
        int o = e >> 5, c = e & 31;
        cwT[c * OO + o] = conv_w[e];
    }

    const int r = tid >> 5, lane = tid & 31;
    const int row = (blockIdx.x << 3) + r;          // row = t*N + n
    const int t = row >> 11, n = row & (NN - 1);
    xs[r][lane] = x[((n * TT + t) << 5) + lane];
    __syncthreads();

    float2 acc = make_float2(0.f, 0.f);
    const float2* cwT2 = (const float2*)cwT;
#pragma unroll
    for (int c = 0; c < CC; c++) {
        float xv = xs[r][c];
        float2 w2 = cwT2[c * 32 + lane];
        acc.x = fmaf(xv, w2.x, acc.x);
        acc.y = fmaf(xv, w2.y, acc.y);
    }
    ((float2*)g_z)[row * 32 + lane] = acc;
}

// ---------------------------------------------------------------------------
// K2: feat[t][n][o] = max_k z[t][A[t][n][k]][o] - z[t][n][o] + conv_b[o]
// One warp per (t,n); lane k holds its neighbor index, broadcast via shfl.
// ---------------------------------------------------------------------------
__global__ __launch_bounds__(256) void k2_gather_max(const int* __restrict__ A,
                                                     const float* __restrict__ conv_b) {
    const int wid = (blockIdx.x << 3) + (threadIdx.x >> 5);  // row = t*N + n
    const int lane = threadIdx.x & 31;
    const int t = wid >> 11;

    const int nb = A[(wid << 5) + lane];  // this lane's neighbor index
    const float2* z2 = (const float2*)g_z;

    float mx = -1e30f, my = -1e30f;
#pragma unroll
    for (int k = 0; k < KK; k++) {
        int r = __shfl_sync(0xffffffffu, nb, k);
        float2 v = __ldg(&z2[(((t << 11) + r) << 5) + lane]);
        mx = fmaxf(mx, v.x);
        my = fmaxf(my, v.y);
    }
    float2 zc = z2[(wid << 5) + lane];
    float2 cb = ((const float2*)conv_b)[lane];
    float2 o;
    o.x = mx - zc.x + cb.x;
    o.y = my - zc.y + cb.y;
    ((float2*)g_feat)[(wid << 5) + lane] = o;
}

// ---------------------------------------------------------------------------
// K3: gates_x[row][o] = feat[row][:] . w_ih[o][:] + (b_ih[o] + b_hh[o])
// Packed f32x2 FMA: w_ih row o held as 32 u64 regs; 32 feat rows staged in
// smem and read as LDS.128 broadcasts; bias folded in at the end.
// ---------------------------------------------------------------------------
__global__ __launch_bounds__(256) void k3_gates_gemm(const float* __restrict__ w_ih,
                                                     const float* __restrict__ b_ih,
                                                     const float* __restrict__ b_hh) {
    __shared__ u64 fs[32 * 32];  // 32 rows x 32 u64 (64 floats)
    const int tid = threadIdx.x;
    const int row0 = blockIdx.x << 5;

    const float4* f4 = (const float4*)(g_feat + (size_t)row0 * OO);
    ((float4*)fs)[tid] = f4[tid];
    ((float4*)fs)[tid + 256] = f4[tid + 256];

    u64 w[32];
    const u64* wp = ((const u64*)w_ih) + tid * 32;
#pragma unroll
    for (int j = 0; j < 32; j++) w[j] = wp[j];
    const float bias = b_ih[tid] + b_hh[tid];
    __syncthreads();

    const ulonglong2* fs2 = (const ulonglong2*)fs;
    for (int r = 0; r < 32; r += 2) {
        u64 a0 = 0ull, a1 = 0ull;
#pragma unroll
        for (int j = 0; j < 16; j++) {
            u64 w0 = w[2 * j], w1 = w[2 * j + 1];
            ulonglong2 f0 = fs2[r * 16 + j];
            ulonglong2 f1 = fs2[r * 16 + 16 + j];
            ffma2(a0, w0, f0.x); ffma2(a0, w1, f0.y);
            ffma2(a1, w0, f1.x); ffma2(a1, w1, f1.y);
        }
        float2 v0 = unpack2(a0), v1 = unpack2(a1);
        g_gates[(size_t)(row0 + r) * G4 + tid] = v0.x + v0.y + bias;
        g_gates[(size_t)(row0 + r + 1) * G4 + tid] = v1.x + v1.y + bias;
    }
}

// ---------------------------------------------------------------------------
// K4: persistent LSTM. 128 blocks x 512 threads; block owns 16 agents for all
// 20 steps (agents independent -> no grid sync). Matvec: thread (o, half)
// computes gate col o for 8 agents with w_hh row in 32 u64 regs (packed FMA);
// gx LDGs issued up-front and folded in after the FMA loop. Update: thread
// owns (agent, 2 channels), c kept in registers.
// ---------------------------------------------------------------------------
__global__ __launch_bounds__(512) void k4_lstm(const float* __restrict__ w_hh,
                                               float* __restrict__ out,
                                               int write_states) {
    __shared__ float h_s[16 * OO];    // h per agent
    __shared__ float g_s[16 * G4];    // gate pre-activations per agent

    const int tid = threadIdx.x;
    const int o = tid & 255;          // gate output column
    const int half = tid >> 8;        // which 8-agent group
    const int ab = blockIdx.x << 4;   // agent base
    const int a0 = half << 3;

    u64 w[32];
    const u64* wp = ((const u64*)w_hh) + o * 32;
#pragma unroll
    for (int j = 0; j < 32; j++) w[j] = wp[j];

    for (int e = tid; e < 16 * OO; e += 512) h_s[e] = 0.f;

    const int a_u = tid >> 5;   // agent for update phase (warp-uniform)
    const int q = tid & 31;     // float2 chunk within 64 channels
    float2 c2 = make_float2(0.f, 0.f);
    __syncthreads();

    for (int t = 0; t < TT; t++) {
        // ---- issue gx loads first; they overlap the whole FMA loop ----
        float gxv[8];
        const float* gx = g_gates + ((size_t)(t << 11) + ab + a0) * G4 + o;
#pragma unroll
        for (int a = 0; a < 8; a++) gxv[a] = gx[(size_t)a << 8];

        u64 acc[8];
#pragma unroll
        for (int a = 0; a < 8; a++) acc[a] = 0ull;

        const ulonglong2* hs2 = (const ulonglong2*)(h_s + (a0 << 6));
#pragma unroll
        for (int j = 0; j < 16; j++) {
            u64 w0 = w[2 * j], w1 = w[2 * j + 1];
#pragma unroll
            for (int a = 0; a < 8; a++) {
                ulonglong2 hv = hs2[(a << 4) + j];
                ffma2(acc[a], w0, hv.x);
                ffma2(acc[a], w1, hv.y);
            }
        }
#pragma unroll
        for (int a = 0; a < 8; a++) {
            float2 v = unpack2(acc[a]);
            g_s[((a0 + a) << 8) + o] = v.x + v.y + gxv[a];
        }
        __syncthreads();

        // ---- nonlinear update: gates order i, f, g, o ----
        const float2* gp = (const float2*)(g_s + (a_u << 8));
        float2 gi = gp[q], gf = gp[32 + q], gg = gp[64 + q], go = gp[96 + q];

        c2.x = sigf(gf.x) * c2.x + sigf(gi.x) * tanhf(gg.x);
        c2.y = sigf(gf.y) * c2.y + sigf(gi.y) * tanhf(gg.y);

        float2 h2;
        h2.x = sigf(go.x) * tanhf(c2.x);
        h2.y = sigf(go.y) * tanhf(c2.y);

        ((float2*)h_s)[(a_u << 5) + q] = h2;
        ((float2*)out)[(((size_t)(ab + a_u) * TT + t) << 5) + q] = h2;  // out[n][t][:]
        __syncthreads();
    }

    if (write_states) {
        float2 h2 = ((const float2*)h_s)[(a_u << 5) + q];
        float2* hn = (float2*)(out + (size_t)NN * TT * OO);
        float2* cn = (float2*)(out + (size_t)NN * TT * OO + (size_t)NN * OO);
        hn[((ab + a_u) << 5) + q] = h2;
        cn[((ab + a_u) << 5) + q] = c2;
    }
}

// ---------------------------------------------------------------------------
extern "C" void kernel_launch(void* const* d_in, const int* in_sizes, int n_in,
                              void* d_out, int out_size) {
    const float* x      = (const float*)d_in[0];
    const int*   A      = (const int*)  d_in[1];
    const float* conv_w = (const float*)d_in[2];
    const float* conv_b = (const float*)d_in[3];
    const float* w_ih   = (const float*)d_in[4];
    const float* w_hh   = (const float*)d_in[5];
    const float* b_ih   = (const float*)d_in[6];
    const float* b_hh   = (const float*)d_in[7];
    float* out = (float*)d_out;

    const long main_sz = (long)NN * TT * OO;
    int write_states = (out_size >= main_sz + 2L * NN * OO) ? 1 : 0;

    k1_project<<<(TT * NN) / 8, 256>>>(x, conv_w);
    k2_gather_max<<<(TT * NN) / 8, 256>>>(A, conv_b);
    k3_gates_gemm<<<(TT * NN) / 32, 256>>>(w_ih, b_ih, b_hh);
    k4_lstm<<<NN / 16, 512>>>(w_hh, out, write_states);
}

// round 3
// speedup vs baseline: 1.0101x; 1.0101x over previous
#include <cuda_runtime.h>
#include <math.h>

#define NN 2048
#define TT 20
#define KK 32
#define CC 32
#define OO 64
#define G4 256   // 4*OO
#define AG 8     // agents per k4 block

// Scratch (static device globals; no runtime allocation)
__device__ float g_z[TT * NN * OO];        // z[t][n][o] = x[n][t] . conv_w[o]
__device__ float g_feat[TT * NN * OO];     // feat[t][n][o]
__device__ float g_gates[TT * NN * G4];    // gates_x[t][n][0..255]

typedef unsigned long long u64;

__device__ __forceinline__ void ffma2(u64& d, u64 a, u64 b) {
    asm("fma.rn.f32x2 %0, %1, %2, %0;" : "+l"(d) : "l"(a), "l"(b));
}
__device__ __forceinline__ float2 unpack2(u64 v) {
    float2 r;
    asm("mov.b64 {%0,%1}, %2;" : "=f"(r.x), "=f"(r.y) : "l"(v));
    return r;
}

__device__ __forceinline__ float sigf(float x) {
    return __fdividef(1.0f, 1.0f + __expf(-x));
}

// ---------------------------------------------------------------------------
// K1: z[t][n][o] = sum_c x[n][t][c] * conv_w[o][c]
// ---------------------------------------------------------------------------
__global__ __launch_bounds__(256) void k1_project(const float* __restrict__ x,
                                                  const float* __restrict__ conv_w) {
    __shared__ float cwT[CC * OO];      // cwT[c*64 + o]
    __shared__ float xs[8][CC];

    const int tid = threadIdx.x;
    for (int e = tid; e < OO * CC; e += 256) {
        int o = e >> 5, c = e & 31;
        cwT[c * OO + o] = conv_w[e];
    }

    const int r = tid >> 5, lane = tid & 31;
    const int row = (blockIdx.x << 3) + r;          // row = t*N + n
    const int t = row >> 11, n = row & (NN - 1);
    xs[r][lane] = x[((n * TT + t) << 5) + lane];
    __syncthreads();

    float2 acc = make_float2(0.f, 0.f);
    const float2* cwT2 = (const float2*)cwT;
#pragma unroll
    for (int c = 0; c < CC; c++) {
        float xv = xs[r][c];
        float2 w2 = cwT2[c * 32 + lane];
        acc.x = fmaf(xv, w2.x, acc.x);
        acc.y = fmaf(xv, w2.y, acc.y);
    }
    ((float2*)g_z)[row * 32 + lane] = acc;
}

// ---------------------------------------------------------------------------
// K2: feat[t][n][o] = max_k z[t][A[t][n][k]][o] - z[t][n][o] + conv_b[o]
// One warp per (t,n); lane k holds its neighbor index, broadcast via shfl.
// ---------------------------------------------------------------------------
__global__ __launch_bounds__(256) void k2_gather_max(const int* __restrict__ A,
                                                     const float* __restrict__ conv_b) {
    const int wid = (blockIdx.x << 3) + (threadIdx.x >> 5);  // row = t*N + n
    const int lane = threadIdx.x & 31;
    const int t = wid >> 11;

    const int nb = A[(wid << 5) + lane];  // this lane's neighbor index
    const float2* z2 = (const float2*)g_z;

    float mx = -1e30f, my = -1e30f;
#pragma unroll
    for (int k = 0; k < KK; k++) {
        int r = __shfl_sync(0xffffffffu, nb, k);
        float2 v = __ldg(&z2[(((t << 11) + r) << 5) + lane]);
        mx = fmaxf(mx, v.x);
        my = fmaxf(my, v.y);
    }
    float2 zc = z2[(wid << 5) + lane];
    float2 cb = ((const float2*)conv_b)[lane];
    float2 o;
    o.x = mx - zc.x + cb.x;
    o.y = my - zc.y + cb.y;
    ((float2*)g_feat)[(wid << 5) + lane] = o;
}

// ---------------------------------------------------------------------------
// K3: gates_x[row][o] = feat[row][:] . w_ih[o][:] + (b_ih[o] + b_hh[o])
// Packed f32x2 FMA: w_ih row o held as 32 u64 regs; 32 feat rows staged in
// smem and read as LDS.128 broadcasts; bias folded in at the end.
// ---------------------------------------------------------------------------
__global__ __launch_bounds__(256) void k3_gates_gemm(const float* __restrict__ w_ih,
                                                     const float* __restrict__ b_ih,
                                                     const float* __restrict__ b_hh) {
    __shared__ u64 fs[32 * 32];  // 32 rows x 32 u64 (64 floats)
    const int tid = threadIdx.x;
    const int row0 = blockIdx.x << 5;

    const float4* f4 = (const float4*)(g_feat + (size_t)row0 * OO);
    ((float4*)fs)[tid] = f4[tid];
    ((float4*)fs)[tid + 256] = f4[tid + 256];

    u64 w[32];
    const u64* wp = ((const u64*)w_ih) + tid * 32;
#pragma unroll
    for (int j = 0; j < 32; j++) w[j] = wp[j];
    const float bias = b_ih[tid] + b_hh[tid];
    __syncthreads();

    const ulonglong2* fs2 = (const ulonglong2*)fs;
    for (int r = 0; r < 32; r += 2) {
        u64 a0 = 0ull, a1 = 0ull;
#pragma unroll
        for (int j = 0; j < 16; j++) {
            u64 w0 = w[2 * j], w1 = w[2 * j + 1];
            ulonglong2 f0 = fs2[r * 16 + j];
            ulonglong2 f1 = fs2[r * 16 + 16 + j];
            ffma2(a0, w0, f0.x); ffma2(a0, w1, f0.y);
            ffma2(a1, w0, f1.x); ffma2(a1, w1, f1.y);
        }
        float2 v0 = unpack2(a0), v1 = unpack2(a1);
        g_gates[(size_t)(row0 + r) * G4 + tid] = v0.x + v0.y + bias;
        g_gates[(size_t)(row0 + r + 1) * G4 + tid] = v1.x + v1.y + bias;
    }
}

// ---------------------------------------------------------------------------
// K4: persistent LSTM. 256 blocks x 256 threads; block owns 8 agents for all
// 20 steps (agents independent -> no grid sync). ~2 blocks/SM so one block's
// barrier/memory stalls are covered by the other block's warps.
// Matvec: thread owns gate col o = tid for all 8 agents; w_hh row o in 32 u64
// regs; h broadcast from smem via LDS.128; packed f32x2 FMA. gx LDGs issued
// up-front to overlap the FMA loop. Update: thread owns (agent, 2 channels),
// c kept in registers.
// ---------------------------------------------------------------------------
__global__ __launch_bounds__(256) void k4_lstm(const float* __restrict__ w_hh,
                                               float* __restrict__ out,
                                               int write_states) {
    __shared__ float h_s[AG * OO];    // h per agent (2 KB)
    __shared__ float g_s[AG * G4];    // gate pre-activations per agent (8 KB)

    const int tid = threadIdx.x;
    const int o = tid;                // gate output column
    const int ab = blockIdx.x * AG;   // agent base

    u64 w[32];
    const u64* wp = ((const u64*)w_hh) + o * 32;
#pragma unroll
    for (int j = 0; j < 32; j++) w[j] = wp[j];

    for (int e = tid; e < AG * OO; e += 256) h_s[e] = 0.f;

    const int a_u = tid >> 5;   // agent for update phase (warp-uniform)
    const int q = tid & 31;     // float2 chunk within 64 channels
    float2 c2 = make_float2(0.f, 0.f);
    __syncthreads();

    for (int t = 0; t < TT; t++) {
        // ---- issue gx loads first; they overlap the whole FMA loop ----
        float gxv[AG];
        const float* gx = g_gates + ((size_t)(t << 11) + ab) * G4 + o;
#pragma unroll
        for (int a = 0; a < AG; a++) gxv[a] = gx[(size_t)a << 8];

        u64 acc[AG];
#pragma unroll
        for (int a = 0; a < AG; a++) acc[a] = 0ull;

        const ulonglong2* hs2 = (const ulonglong2*)h_s;
#pragma unroll
        for (int j = 0; j < 16; j++) {
            u64 w0 = w[2 * j], w1 = w[2 * j + 1];
#pragma unroll
            for (int a = 0; a < AG; a++) {
                ulonglong2 hv = hs2[(a << 4) + j];
                ffma2(acc[a], w0, hv.x);
                ffma2(acc[a], w1, hv.y);
            }
        }
#pragma unroll
        for (int a = 0; a < AG; a++) {
            float2 v = unpack2(acc[a]);
            g_s[(a << 8) + o] = v.x + v.y + gxv[a];
        }
        __syncthreads();

        // ---- nonlinear update: gates order i, f, g, o ----
        const float2* gp = (const float2*)(g_s + (a_u << 8));
        float2 gi = gp[q], gf = gp[32 + q], gg = gp[64 + q], go = gp[96 + q];

        c2.x = sigf(gf.x) * c2.x + sigf(gi.x) * tanhf(gg.x);
        c2.y = sigf(gf.y) * c2.y + sigf(gi.y) * tanhf(gg.y);

        float2 h2;
        h2.x = sigf(go.x) * tanhf(c2.x);
        h2.y = sigf(go.y) * tanhf(c2.y);

        ((float2*)h_s)[(a_u << 5) + q] = h2;
        ((float2*)out)[(((size_t)(ab + a_u) * TT + t) << 5) + q] = h2;  // out[n][t][:]
        __syncthreads();
    }

    if (write_states) {
        float2 h2 = ((const float2*)h_s)[(a_u << 5) + q];
        float2* hn = (float2*)(out + (size_t)NN * TT * OO);
        float2* cn = (float2*)(out + (size_t)NN * TT * OO + (size_t)NN * OO);
        hn[((ab + a_u) << 5) + q] = h2;
        cn[((ab + a_u) << 5) + q] = c2;
    }
}

// ---------------------------------------------------------------------------
extern "C" void kernel_launch(void* const* d_in, const int* in_sizes, int n_in,
                              void* d_out, int out_size) {
    const float* x      = (const float*)d_in[0];
    const int*   A      = (const int*)  d_in[1];
    const float* conv_w = (const float*)d_in[2];
    const float* conv_b = (const float*)d_in[3];
    const float* w_ih   = (const float*)d_in[4];
    const float* w_hh   = (const float*)d_in[5];
    const float* b_ih   = (const float*)d_in[6];
    const float* b_hh   = (const float*)d_in[7];
    float* out = (float*)d_out;

    const long main_sz = (long)NN * TT * OO;
    int write_states = (out_size >= main_sz + 2L * NN * OO) ? 1 : 0;

    k1_project<<<(TT * NN) / 8, 256>>>(x, conv_w);
    k2_gather_max<<<(TT * NN) / 8, 256>>>(A, conv_b);
    k3_gates_gemm<<<(TT * NN) / 32, 256>>>(w_ih, b_ih, b_hh);
    k4_lstm<<<NN / AG, 256>>>(w_hh, out, write_states);
}

// round 4
// speedup vs baseline: 1.0356x; 1.0253x over previous
#include <cuda_runtime.h>
#include <cuda_fp16.h>
#include <math.h>

#define NN 2048
#define TT 20
#define KK 32
#define CC 32
#define OO 64
#define G4 256   // 4*OO
#define AG 8     // agents per k4 block

// Scratch (static device globals; no runtime allocation)
__device__ float   g_z[TT * NN * OO];       // z[t][n][o] f32 (center term)
__device__ __half2 g_zh[TT * NN * (OO/2)];  // z fp16 copy (gather/max term)
__device__ float   g_feat[TT * NN * OO];    // feat[t][n][o]
__device__ float   g_gates[TT * NN * G4];   // gates_x[t][n][0..255]

typedef unsigned long long u64;

__device__ __forceinline__ void ffma2(u64& d, u64 a, u64 b) {
    asm("fma.rn.f32x2 %0, %1, %2, %0;" : "+l"(d) : "l"(a), "l"(b));
}
__device__ __forceinline__ float2 unpack2(u64 v) {
    float2 r;
    asm("mov.b64 {%0,%1}, %2;" : "=f"(r.x), "=f"(r.y) : "l"(v));
    return r;
}

// NaN-safe fast sigmoid / tanh (rel err ~1e-7, 2 MUFU each)
__device__ __forceinline__ float sigf(float x) {
    return __fdividef(1.0f, 1.0f + __expf(-x));
}
__device__ __forceinline__ float tanhf_fast(float x) {
    // tanh(x) = 1 - 2/(exp(2x)+1); exp->inf gives 1, exp->0 gives -1 (no NaN)
    return 1.0f - __fdividef(2.0f, __expf(2.0f * x) + 1.0f);
}

// ---------------------------------------------------------------------------
// K1: z[t][n][o] = sum_c x[n][t][c] * conv_w[o][c]; writes f32 + fp16 copies.
// ---------------------------------------------------------------------------
__global__ __launch_bounds__(256) void k1_project(const float* __restrict__ x,
                                                  const float* __restrict__ conv_w) {
    __shared__ float cwT[CC * OO];      // cwT[c*64 + o]
    __shared__ float xs[8][CC];

    const int tid = threadIdx.x;
    for (int e = tid; e < OO * CC; e += 256) {
        int o = e >> 5, c = e & 31;
        cwT[c * OO + o] = conv_w[e];
    }

    const int r = tid >> 5, lane = tid & 31;
    const int row = (blockIdx.x << 3) + r;          // row = t*N + n
    const int t = row >> 11, n = row & (NN - 1);
    xs[r][lane] = x[((n * TT + t) << 5) + lane];
    __syncthreads();

    float2 acc = make_float2(0.f, 0.f);
    const float2* cwT2 = (const float2*)cwT;
#pragma unroll
    for (int c = 0; c < CC; c++) {
        float xv = xs[r][c];
        float2 w2 = cwT2[c * 32 + lane];
        acc.x = fmaf(xv, w2.x, acc.x);
        acc.y = fmaf(xv, w2.y, acc.y);
    }
    ((float2*)g_z)[row * 32 + lane] = acc;
    g_zh[row * 32 + lane] = __floats2half2_rn(acc.x, acc.y);
}

// ---------------------------------------------------------------------------
// K2: feat[t][n][o] = max_k zh[t][A[t][n][k]][o] - z[t][n][o] + conv_b[o]
// One warp per (t,n); lane k holds its neighbor index, broadcast via shfl.
// Gather in fp16 (max is order-preserving under monotone quantization);
// center z and bias stay f32. 128B per gathered row (one L2 line).
// ---------------------------------------------------------------------------
__global__ __launch_bounds__(256) void k2_gather_max(const int* __restrict__ A,
                                                     const float* __restrict__ conv_b) {
    const int wid = (blockIdx.x << 3) + (threadIdx.x >> 5);  // row = t*N + n
    const int lane = threadIdx.x & 31;
    const int t = wid >> 11;

    const int nb = A[(wid << 5) + lane];  // this lane's neighbor index
    const __half2* zh = g_zh;

    __half2 m = __float2half2_rn(-60000.f);
#pragma unroll
    for (int k = 0; k < KK; k++) {
        int r = __shfl_sync(0xffffffffu, nb, k);
        __half2 v = __ldg(&zh[(((t << 11) + r) << 5) + lane]);
        m = __hmax2(m, v);
    }
    float2 mf = __half22float2(m);
    float2 zc = ((const float2*)g_z)[(wid << 5) + lane];
    float2 cb = ((const float2*)conv_b)[lane];
    float2 o;
    o.x = mf.x - zc.x + cb.x;
    o.y = mf.y - zc.y + cb.y;
    ((float2*)g_feat)[(wid << 5) + lane] = o;
}

// ---------------------------------------------------------------------------
// K3: gates_x[row][o] = feat[row][:] . w_ih[o][:] + (b_ih[o] + b_hh[o])
// Packed f32x2 FMA: w_ih row o held as 32 u64 regs; 32 feat rows staged in
// smem and read as LDS.128 broadcasts; bias folded in at the end.
// ---------------------------------------------------------------------------
__global__ __launch_bounds__(256) void k3_gates_gemm(const float* __restrict__ w_ih,
                                                     const float* __restrict__ b_ih,
                                                     const float* __restrict__ b_hh) {
    __shared__ u64 fs[32 * 32];  // 32 rows x 32 u64 (64 floats)
    const int tid = threadIdx.x;
    const int row0 = blockIdx.x << 5;

    const float4* f4 = (const float4*)(g_feat + (size_t)row0 * OO);
    ((float4*)fs)[tid] = f4[tid];
    ((float4*)fs)[tid + 256] = f4[tid + 256];

    u64 w[32];
    const u64* wp = ((const u64*)w_ih) + tid * 32;
#pragma unroll
    for (int j = 0; j < 32; j++) w[j] = wp[j];
    const float bias = b_ih[tid] + b_hh[tid];
    __syncthreads();

    const ulonglong2* fs2 = (const ulonglong2*)fs;
    for (int r = 0; r < 32; r += 2) {
        u64 a0 = 0ull, a1 = 0ull;
#pragma unroll
        for (int j = 0; j < 16; j++) {
            u64 w0 = w[2 * j], w1 = w[2 * j + 1];
            ulonglong2 f0 = fs2[r * 16 + j];
            ulonglong2 f1 = fs2[r * 16 + 16 + j];
            ffma2(a0, w0, f0.x); ffma2(a0, w1, f0.y);
            ffma2(a1, w0, f1.x); ffma2(a1, w1, f1.y);
        }
        float2 v0 = unpack2(a0), v1 = unpack2(a1);
        g_gates[(size_t)(row0 + r) * G4 + tid] = v0.x + v0.y + bias;
        g_gates[(size_t)(row0 + r + 1) * G4 + tid] = v1.x + v1.y + bias;
    }
}

// ---------------------------------------------------------------------------
// K4: persistent LSTM. 256 blocks x 256 threads; block owns 8 agents for all
// 20 steps; ~2 blocks/SM so one block's barrier/memory stalls are covered by
// the other block. Matvec: thread owns gate col o for all 8 agents, w_hh row
// in 32 u64 regs, h broadcast via LDS.128, packed f32x2 FMA. Update: thread
// owns (agent, 2 channels), c in registers, fast 2-MUFU sigmoid/tanh.
// ---------------------------------------------------------------------------
__global__ __launch_bounds__(256) void k4_lstm(const float* __restrict__ w_hh,
                                               float* __restrict__ out,
                                               int write_states) {
    __shared__ float h_s[AG * OO];    // h per agent (2 KB)
    __shared__ float g_s[AG * G4];    // gate pre-activations per agent (8 KB)

    const int tid = threadIdx.x;
    const int o = tid;                // gate output column
    const int ab = blockIdx.x * AG;   // agent base

    u64 w[32];
    const u64* wp = ((const u64*)w_hh) + o * 32;
#pragma unroll
    for (int j = 0; j < 32; j++) w[j] = wp[j];

    for (int e = tid; e < AG * OO; e += 256) h_s[e] = 0.f;

    const int a_u = tid >> 5;   // agent for update phase (warp-uniform)
    const int q = tid & 31;     // float2 chunk within 64 channels
    float2 c2 = make_float2(0.f, 0.f);
    __syncthreads();

    for (int t = 0; t < TT; t++) {
        // ---- issue gx loads first; they overlap the whole FMA loop ----
        float gxv[AG];
        const float* gx = g_gates + ((size_t)(t << 11) + ab) * G4 + o;
#pragma unroll
        for (int a = 0; a < AG; a++) gxv[a] = gx[(size_t)a << 8];

        u64 acc[AG];
#pragma unroll
        for (int a = 0; a < AG; a++) acc[a] = 0ull;

        const ulonglong2* hs2 = (const ulonglong2*)h_s;
#pragma unroll
        for (int j = 0; j < 16; j++) {
            u64 w0 = w[2 * j], w1 = w[2 * j + 1];
#pragma unroll
            for (int a = 0; a < AG; a++) {
                ulonglong2 hv = hs2[(a << 4) + j];
                ffma2(acc[a], w0, hv.x);
                ffma2(acc[a], w1, hv.y);
            }
        }
#pragma unroll
        for (int a = 0; a < AG; a++) {
            float2 v = unpack2(acc[a]);
            g_s[(a << 8) + o] = v.x + v.y + gxv[a];
        }
        __syncthreads();

        // ---- nonlinear update: gates order i, f, g, o ----
        const float2* gp = (const float2*)(g_s + (a_u << 8));
        float2 gi = gp[q], gf = gp[32 + q], gg = gp[64 + q], go = gp[96 + q];

        c2.x = sigf(gf.x) * c2.x + sigf(gi.x) * tanhf_fast(gg.x);
        c2.y = sigf(gf.y) * c2.y + sigf(gi.y) * tanhf_fast(gg.y);

        float2 h2;
        h2.x = sigf(go.x) * tanhf_fast(c2.x);
        h2.y = sigf(go.y) * tanhf_fast(c2.y);

        ((float2*)h_s)[(a_u << 5) + q] = h2;
        ((float2*)out)[(((size_t)(ab + a_u) * TT + t) << 5) + q] = h2;  // out[n][t][:]
        __syncthreads();
    }

    if (write_states) {
        float2 h2 = ((const float2*)h_s)[(a_u << 5) + q];
        float2* hn = (float2*)(out + (size_t)NN * TT * OO);
        float2* cn = (float2*)(out + (size_t)NN * TT * OO + (size_t)NN * OO);
        hn[((ab + a_u) << 5) + q] = h2;
        cn[((ab + a_u) << 5) + q] = c2;
    }
}

// ---------------------------------------------------------------------------
extern "C" void kernel_launch(void* const* d_in, const int* in_sizes, int n_in,
                              void* d_out, int out_size) {
    const float* x      = (const float*)d_in[0];
    const int*   A      = (const int*)  d_in[1];
    const float* conv_w = (const float*)d_in[2];
    const float* conv_b = (const float*)d_in[3];
    const float* w_ih   = (const float*)d_in[4];
    const float* w_hh   = (const float*)d_in[5];
    const float* b_ih   = (const float*)d_in[6];
    const float* b_hh   = (const float*)d_in[7];
    float* out = (float*)d_out;

    const long main_sz = (long)NN * TT * OO;
    int write_states = (out_size >= main_sz + 2L * NN * OO) ? 1 : 0;

    k1_project<<<(TT * NN) / 8, 256>>>(x, conv_w);
    k2_gather_max<<<(TT * NN) / 8, 256>>>(A, conv_b);
    k3_gates_gemm<<<(TT * NN) / 32, 256>>>(w_ih, b_ih, b_hh);
    k4_lstm<<<NN / AG, 256>>>(w_hh, out, write_states);
}